// round 1
// baseline (speedup 1.0000x reference)
#include <cuda_runtime.h>
#include <cuda_bf16.h>
#include <math.h>

#define N_NODES 16384
#define NGLOB   4
#define NTOTAL  (N_NODES + NGLOB)
#define DIM     256
#define HEADS   8
#define DHEAD   32
#define E_LOCAL 131072
#define E_EXP   65536
#define E_CSR   (E_LOCAL + E_EXP)

// ---------------- scratch (static device allocations only) ----------------
__device__ float g_qkv[(size_t)NTOTAL * 3 * DIM];   // [row][q|k|v (256 each)]
__device__ float g_attn[(size_t)N_NODES * DIM];
__device__ int   g_count[N_NODES];
__device__ int   g_off[N_NODES + 1];
__device__ int   g_wptr[N_NODES];
__device__ int   g_srcbuf[E_CSR];

// ---------------- CSR build ----------------
__global__ void zero_counts_kernel() {
    int t = blockIdx.x * blockDim.x + threadIdx.x;
    if (t < N_NODES) g_count[t] = 0;
}

__global__ void count_kernel(const int* __restrict__ ei, const int* __restrict__ xi) {
    int t = blockIdx.x * blockDim.x + threadIdx.x;
    if (t < E_LOCAL) atomicAdd(&g_count[ei[E_LOCAL + t]], 1);
    if (t < E_EXP)   atomicAdd(&g_count[xi[E_EXP + t]], 1);
}

__global__ void scan_kernel() {
    __shared__ int s[1024];
    __shared__ int carry_s;
    int tid = threadIdx.x;
    if (tid == 0) carry_s = 0;
    __syncthreads();
    for (int base = 0; base < N_NODES; base += 1024) {
        int v = g_count[base + tid];
        s[tid] = v;
        __syncthreads();
        for (int o = 1; o < 1024; o <<= 1) {
            int t = (tid >= o) ? s[tid - o] : 0;
            __syncthreads();
            s[tid] += t;
            __syncthreads();
        }
        int carry = carry_s;
        int excl  = carry + s[tid] - v;
        g_off[base + tid]  = excl;
        g_wptr[base + tid] = excl;
        __syncthreads();
        if (tid == 1023) carry_s = carry + s[1023];
        __syncthreads();
    }
    if (tid == 0) g_off[N_NODES] = carry_s;
}

__global__ void fill_kernel(const int* __restrict__ ei, const int* __restrict__ xi) {
    int t = blockIdx.x * blockDim.x + threadIdx.x;
    if (t < E_LOCAL) {
        int d = ei[E_LOCAL + t];
        int p = atomicAdd(&g_wptr[d], 1);
        g_srcbuf[p] = ei[t];
    }
    if (t < E_EXP) {
        int d = xi[E_EXP + t];
        int p = atomicAdd(&g_wptr[d], 1);
        g_srcbuf[p] = xi[t];
    }
}

// ---------------- fp32 SGEMM: C[M,N] = rowsel(A,Aext)[M,256] * W[256,N] + b ----------------
// BM=BN=128, BK=8, 256 threads, 8x8 microtile.
__global__ __launch_bounds__(256) void gemm_bias_kernel(
    const float* __restrict__ A, const float* __restrict__ Aext, int Msplit,
    int M, int Ncols,
    const float* __restrict__ W, const float* __restrict__ bias,
    float* __restrict__ C)
{
    __shared__ float As[8][132];   // transposed A tile, padded (row stride 132 floats = 16B aligned)
    __shared__ float Ws[8][132];

    const int tid  = threadIdx.x;
    const int row0 = blockIdx.y * 128;
    const int col0 = blockIdx.x * 128;
    const int tx = tid & 15;        // col group
    const int ty = tid >> 4;        // row group

    float acc[8][8];
#pragma unroll
    for (int i = 0; i < 8; i++)
#pragma unroll
        for (int j = 0; j < 8; j++) acc[i][j] = 0.f;

    for (int k0 = 0; k0 < DIM; k0 += 8) {
        // Load A tile (128 rows x 8 k) -> As[k][m] transposed.
        {
            int m  = tid >> 1;            // 0..127
            int kq = tid & 1;             // which float4 of the 8 k's
            int gr = row0 + m;
            float4 v = make_float4(0.f, 0.f, 0.f, 0.f);
            if (gr < M) {
                const float* srcp = (gr < Msplit) ? (A + (size_t)gr * DIM)
                                                  : (Aext + (size_t)(gr - Msplit) * DIM);
                v = *(const float4*)(srcp + k0 + kq * 4);
            }
            As[kq * 4 + 0][m] = v.x;
            As[kq * 4 + 1][m] = v.y;
            As[kq * 4 + 2][m] = v.z;
            As[kq * 4 + 3][m] = v.w;
        }
        // Load W tile (8 k x 128 n) -> Ws[k][n].
        {
            int k  = tid >> 5;            // 0..7
            int nq = tid & 31;            // 32 float4 per row
            float4 v = *(const float4*)(W + (size_t)(k0 + k) * Ncols + col0 + nq * 4);
            *(float4*)&Ws[k][nq * 4] = v;
        }
        __syncthreads();

#pragma unroll
        for (int k = 0; k < 8; k++) {
            float a[8], w[8];
            *(float4*)&a[0] = *(const float4*)&As[k][ty * 8];
            *(float4*)&a[4] = *(const float4*)&As[k][ty * 8 + 4];
            *(float4*)&w[0] = *(const float4*)&Ws[k][tx * 8];
            *(float4*)&w[4] = *(const float4*)&Ws[k][tx * 8 + 4];
#pragma unroll
            for (int i = 0; i < 8; i++)
#pragma unroll
                for (int j = 0; j < 8; j++) acc[i][j] += a[i] * w[j];
        }
        __syncthreads();
    }

#pragma unroll
    for (int i = 0; i < 8; i++) {
        int r = row0 + ty * 8 + i;
        if (r >= M) continue;
#pragma unroll
        for (int j = 0; j < 8; j++) {
            int c = col0 + tx * 8 + j;
            C[(size_t)r * Ncols + c] = acc[i][j] + bias[c];
        }
    }
}

// ---------------- attention: one warp per destination node, all 8 heads ----------------
__global__ __launch_bounds__(256) void attn_kernel() {
    int gw = (blockIdx.x * blockDim.x + threadIdx.x) >> 5;
    if (gw >= N_NODES) return;
    const int lane = threadIdx.x & 31;           // lane = head*4 + quarter
    const float scale = 0.17677669529663687f;    // 32^-0.5

    // Q for this dst: each lane owns 8 consecutive dims of its head.
    const float* Qp = g_qkv + (size_t)gw * 768 + (lane << 3);
    float q[8];
    {
        float4 q0 = *(const float4*)Qp;
        float4 q1 = *(const float4*)(Qp + 4);
        q[0] = q0.x * scale; q[1] = q0.y * scale; q[2] = q0.z * scale; q[3] = q0.w * scale;
        q[4] = q1.x * scale; q[5] = q1.y * scale; q[6] = q1.z * scale; q[7] = q1.w * scale;
    }

    float m = -INFINITY, l = 0.f;
    float acc[8];
#pragma unroll
    for (int i = 0; i < 8; i++) acc[i] = 0.f;

    const int s0   = g_off[gw];
    const int nloc = g_off[gw + 1] - s0;
    const int ntot = nloc + 1 + NGLOB;           // csr + self + globals

    for (int it = 0; it < ntot; it++) {
        int src;
        if (it < nloc)          src = g_srcbuf[s0 + it];
        else if (it == nloc)    src = gw;                       // self loop
        else                    src = N_NODES + (it - nloc - 1); // global tokens

        const float* Kp = g_qkv + (size_t)src * 768 + 256 + (lane << 3);
        float4 k0 = *(const float4*)Kp;
        float4 k1 = *(const float4*)(Kp + 4);
        float dot = q[0]*k0.x + q[1]*k0.y + q[2]*k0.z + q[3]*k0.w
                  + q[4]*k1.x + q[5]*k1.y + q[6]*k1.z + q[7]*k1.w;
        dot += __shfl_xor_sync(0xFFFFFFFFu, dot, 1);
        dot += __shfl_xor_sync(0xFFFFFFFFu, dot, 2);

        float mnew = fmaxf(m, dot);
        float corr = __expf(m - mnew);           // exp(-inf)=0 handles first edge
        float w    = __expf(dot - mnew);
        l = l * corr + w;

        const float* Vp = Kp + 256;
        float4 v0 = *(const float4*)Vp;
        float4 v1 = *(const float4*)(Vp + 4);
        acc[0] = acc[0] * corr + w * v0.x;
        acc[1] = acc[1] * corr + w * v0.y;
        acc[2] = acc[2] * corr + w * v0.z;
        acc[3] = acc[3] * corr + w * v0.w;
        acc[4] = acc[4] * corr + w * v1.x;
        acc[5] = acc[5] * corr + w * v1.y;
        acc[6] = acc[6] * corr + w * v1.z;
        acc[7] = acc[7] * corr + w * v1.w;
        m = mnew;
    }

    float inv = 1.f / l;
    float* outp = g_attn + (size_t)gw * 256 + (lane << 3);
#pragma unroll
    for (int i = 0; i < 8; i++) outp[i] = acc[i] * inv;
}

// ---------------- launch ----------------
extern "C" void kernel_launch(void* const* d_in, const int* in_sizes, int n_in,
                              void* d_out, int out_size) {
    const float* x      = (const float*)d_in[0];
    const int*   ei     = (const int*)d_in[1];
    const int*   xi     = (const int*)d_in[2];
    const float* W_qkv  = (const float*)d_in[3];
    const float* b_qkv  = (const float*)d_in[4];
    const float* W_out  = (const float*)d_in[5];
    const float* b_out  = (const float*)d_in[6];
    const float* gtok   = (const float*)d_in[7];
    float* out = (float*)d_out;

    float* qkv_ptr;   cudaGetSymbolAddress((void**)&qkv_ptr, g_qkv);
    float* attn_ptr;  cudaGetSymbolAddress((void**)&attn_ptr, g_attn);

    // CSR build
    zero_counts_kernel<<<N_NODES / 256, 256>>>();
    count_kernel<<<(E_LOCAL + 255) / 256, 256>>>(ei, xi);
    scan_kernel<<<1, 1024>>>();
    fill_kernel<<<(E_LOCAL + 255) / 256, 256>>>(ei, xi);

    // QKV projection: [16388, 256] x [256, 768] + b
    {
        dim3 grid(3 * DIM / 128, (NTOTAL + 127) / 128);
        gemm_bias_kernel<<<grid, 256>>>(x, gtok, N_NODES, NTOTAL, 3 * DIM,
                                        W_qkv, b_qkv, qkv_ptr);
    }

    // attention: one warp per node
    attn_kernel<<<(N_NODES * 32) / 256, 256>>>();

    // out projection: [16384, 256] x [256, 256] + b
    {
        dim3 grid(DIM / 128, N_NODES / 128);
        gemm_bias_kernel<<<grid, 256>>>(attn_ptr, attn_ptr, N_NODES, N_NODES, DIM,
                                        W_out, b_out, out);
    }
}

// round 3
// speedup vs baseline: 1.5356x; 1.5356x over previous
#include <cuda_runtime.h>
#include <cuda_bf16.h>
#include <math.h>
#include <stdint.h>

#define N_NODES 16384
#define NGLOB   4
#define NTOTAL  (N_NODES + NGLOB)
#define DIM     256
#define HEADS   8
#define DHEAD   32
#define E_LOCAL 131072
#define E_EXP   65536
#define E_CSR   (E_LOCAL + E_EXP)

// ---------------- scratch (static device allocations only) ----------------
__device__ float g_qkv[(size_t)NTOTAL * 3 * DIM];   // [row][q|k|v (256 each)]
__device__ float g_attn[(size_t)N_NODES * DIM];
__device__ int   g_count[N_NODES];
__device__ int   g_off[N_NODES + 1];
__device__ int   g_wptr[N_NODES];
__device__ int   g_srcbuf[E_CSR];

// ---------------- CSR build ----------------
__global__ void zero_counts_kernel() {
    int t = blockIdx.x * blockDim.x + threadIdx.x;
    if (t < N_NODES) g_count[t] = 0;
}

__global__ void count_kernel(const int* __restrict__ ei, const int* __restrict__ xi) {
    int t = blockIdx.x * blockDim.x + threadIdx.x;
    if (t < E_LOCAL) atomicAdd(&g_count[ei[E_LOCAL + t]], 1);
    if (t < E_EXP)   atomicAdd(&g_count[xi[E_EXP + t]], 1);
}

// Single-pass hierarchical scan: 512 threads x 32 nodes each.
__global__ __launch_bounds__(512) void scan_kernel() {
    const int tid  = threadIdx.x;
    const int lane = tid & 31;
    const int wid  = tid >> 5;
    const int base = tid * 32;

    int vals[32];
#pragma unroll
    for (int i = 0; i < 32; i += 4) {
        int4 t = *(const int4*)&g_count[base + i];
        vals[i] = t.x; vals[i+1] = t.y; vals[i+2] = t.z; vals[i+3] = t.w;
    }
    int sum = 0;
#pragma unroll
    for (int i = 0; i < 32; i++) { int v = vals[i]; vals[i] = sum; sum += v; } // exclusive local

    // warp inclusive scan of thread sums
    int inc = sum;
#pragma unroll
    for (int o = 1; o < 32; o <<= 1) {
        int n = __shfl_up_sync(0xFFFFFFFFu, inc, o);
        if (lane >= o) inc += n;
    }
    __shared__ int wsum[16];
    if (lane == 31) wsum[wid] = inc;
    __syncthreads();
    if (wid == 0) {
        int w = (lane < 16) ? wsum[lane] : 0;
#pragma unroll
        for (int o = 1; o < 16; o <<= 1) {
            int n = __shfl_up_sync(0xFFFFFFFFu, w, o);
            if (lane >= o) w += n;
        }
        if (lane < 16) wsum[lane] = w;
    }
    __syncthreads();

    int offset = (wid ? wsum[wid - 1] : 0) + inc - sum;
#pragma unroll
    for (int i = 0; i < 32; i++) {
        int o = offset + vals[i];
        g_off[base + i]  = o;
        g_wptr[base + i] = o;
    }
    if (tid == 511) g_off[N_NODES] = wsum[15];
}

__global__ void fill_kernel(const int* __restrict__ ei, const int* __restrict__ xi) {
    int t = blockIdx.x * blockDim.x + threadIdx.x;
    if (t < E_LOCAL) {
        int d = ei[E_LOCAL + t];
        int p = atomicAdd(&g_wptr[d], 1);
        g_srcbuf[p] = ei[t];
    }
    if (t < E_EXP) {
        int d = xi[E_EXP + t];
        int p = atomicAdd(&g_wptr[d], 1);
        g_srcbuf[p] = xi[t];
    }
}

// ---------------- split-bf16 tensor-core GEMM ----------------
// C[M,Ncols] = rowsel(A,Aext)[M,256] * W[256,Ncols] + bias
// x = hi + lo (bf16 each); C += hi*hi + hi*lo + lo*hi via mma.m16n8k16.bf16
// BM=128, BN=128, BK=32. 256 threads = 8 warps; warp tile 32(m) x 64(n).

__device__ __forceinline__ uint32_t smem_u32(const void* p) {
    return (uint32_t)__cvta_generic_to_shared(p);
}

__device__ __forceinline__ void ldsm_x4(uint32_t addr, uint32_t& r0, uint32_t& r1,
                                        uint32_t& r2, uint32_t& r3) {
    asm volatile("ldmatrix.sync.aligned.m8n8.x4.shared.b16 {%0,%1,%2,%3}, [%4];"
                 : "=r"(r0), "=r"(r1), "=r"(r2), "=r"(r3) : "r"(addr));
}
__device__ __forceinline__ void ldsm_x4_t(uint32_t addr, uint32_t& r0, uint32_t& r1,
                                          uint32_t& r2, uint32_t& r3) {
    asm volatile("ldmatrix.sync.aligned.m8n8.x4.trans.shared.b16 {%0,%1,%2,%3}, [%4];"
                 : "=r"(r0), "=r"(r1), "=r"(r2), "=r"(r3) : "r"(addr));
}
__device__ __forceinline__ void mma_bf16(float* d, const uint32_t* a, const uint32_t* b) {
    asm volatile(
        "mma.sync.aligned.m16n8k16.row.col.f32.bf16.bf16.f32 "
        "{%0,%1,%2,%3},{%4,%5,%6,%7},{%8,%9},{%0,%1,%2,%3};"
        : "+f"(d[0]), "+f"(d[1]), "+f"(d[2]), "+f"(d[3])
        : "r"(a[0]), "r"(a[1]), "r"(a[2]), "r"(a[3]), "r"(b[0]), "r"(b[1]));
}

#define APAD 40    // smem k-stride for A (bf16 units): conflict-free ldmatrix rows
#define BPAD 136   // smem n-stride for B (bf16 units)

__global__ __launch_bounds__(256) void gemm_bias_tc_kernel(
    const float* __restrict__ A, const float* __restrict__ Aext, int Msplit,
    int M, int Ncols,
    const float* __restrict__ W, const float* __restrict__ bias,
    float* __restrict__ C)
{
    __shared__ __nv_bfloat16 As[2][128][APAD];   // [hi/lo][m][k]
    __shared__ __nv_bfloat16 Bs[2][32][BPAD];    // [hi/lo][k][n]

    const int tid    = threadIdx.x;
    const int lane   = tid & 31;
    const int warp   = tid >> 5;
    const int warp_m = warp & 3;      // 4 -> m offset *32
    const int warp_n = warp >> 2;     // 2 -> n offset *64
    const int row0   = blockIdx.y * 128;
    const int col0   = blockIdx.x * 128;

    float acc[2][8][4];
#pragma unroll
    for (int i = 0; i < 2; i++)
#pragma unroll
        for (int j = 0; j < 8; j++)
#pragma unroll
            for (int q = 0; q < 4; q++) acc[i][j][q] = 0.f;

    // A-load mapping: thread -> row, 4 float4 per thread
    const int a_row = tid >> 1;
    const int a_q   = tid & 1;
    const int gr    = row0 + a_row;
    const bool a_ok = (gr < M);
    const float* a_src = a_ok ? ((gr < Msplit) ? (A + (size_t)gr * DIM)
                                               : (Aext + (size_t)(gr - Msplit) * DIM))
                              : A;  // dummy, guarded

    // B-load mapping
    const int b_k  = tid >> 3;
    const int b_n0 = (tid & 7) * 16;

    // fragment addresses
    const int fa_row  = warp_m * 32 + (lane & 15);
    const int fa_koff = (lane >> 4) << 3;
    const int fb_krow = (((lane >> 3) & 1) << 3) + (lane & 7);
    const int fb_n    = warp_n * 64 + ((lane >> 4) << 3);

    for (int k0 = 0; k0 < DIM; k0 += 32) {
        // ---- load + convert A tile ----
#pragma unroll
        for (int i = 0; i < 4; i++) {
            int kk = (a_q * 4 + i) * 4;
            float4 v = make_float4(0.f, 0.f, 0.f, 0.f);
            if (a_ok) v = *(const float4*)(a_src + k0 + kk);
            __nv_bfloat16 h0 = __float2bfloat16(v.x), h1 = __float2bfloat16(v.y);
            __nv_bfloat16 h2 = __float2bfloat16(v.z), h3 = __float2bfloat16(v.w);
            __nv_bfloat16 l0 = __float2bfloat16(v.x - __bfloat162float(h0));
            __nv_bfloat16 l1 = __float2bfloat16(v.y - __bfloat162float(h1));
            __nv_bfloat16 l2 = __float2bfloat16(v.z - __bfloat162float(h2));
            __nv_bfloat16 l3 = __float2bfloat16(v.w - __bfloat162float(h3));
            *(__nv_bfloat162*)&As[0][a_row][kk]     = __nv_bfloat162(h0, h1);
            *(__nv_bfloat162*)&As[0][a_row][kk + 2] = __nv_bfloat162(h2, h3);
            *(__nv_bfloat162*)&As[1][a_row][kk]     = __nv_bfloat162(l0, l1);
            *(__nv_bfloat162*)&As[1][a_row][kk + 2] = __nv_bfloat162(l2, l3);
        }
        // ---- load + convert B tile (row-major [k][n]) ----
        {
            const float* wrow = W + (size_t)(k0 + b_k) * Ncols + col0 + b_n0;
#pragma unroll
            for (int i = 0; i < 4; i++) {
                float4 v = *(const float4*)(wrow + i * 4);
                int nn = b_n0 + i * 4;
                __nv_bfloat16 h0 = __float2bfloat16(v.x), h1 = __float2bfloat16(v.y);
                __nv_bfloat16 h2 = __float2bfloat16(v.z), h3 = __float2bfloat16(v.w);
                __nv_bfloat16 l0 = __float2bfloat16(v.x - __bfloat162float(h0));
                __nv_bfloat16 l1 = __float2bfloat16(v.y - __bfloat162float(h1));
                __nv_bfloat16 l2 = __float2bfloat16(v.z - __bfloat162float(h2));
                __nv_bfloat16 l3 = __float2bfloat16(v.w - __bfloat162float(h3));
                *(__nv_bfloat162*)&Bs[0][b_k][nn]     = __nv_bfloat162(h0, h1);
                *(__nv_bfloat162*)&Bs[0][b_k][nn + 2] = __nv_bfloat162(h2, h3);
                *(__nv_bfloat162*)&Bs[1][b_k][nn]     = __nv_bfloat162(l0, l1);
                *(__nv_bfloat162*)&Bs[1][b_k][nn + 2] = __nv_bfloat162(l2, l3);
            }
        }
        __syncthreads();

#pragma unroll
        for (int ks = 0; ks < 32; ks += 16) {
            uint32_t ah[2][4], al[2][4], bh[8][2], bl[8][2];
#pragma unroll
            for (int mt = 0; mt < 2; mt++) {
                ldsm_x4(smem_u32(&As[0][fa_row + mt * 16][ks + fa_koff]),
                        ah[mt][0], ah[mt][1], ah[mt][2], ah[mt][3]);
                ldsm_x4(smem_u32(&As[1][fa_row + mt * 16][ks + fa_koff]),
                        al[mt][0], al[mt][1], al[mt][2], al[mt][3]);
            }
#pragma unroll
            for (int np = 0; np < 4; np++) {
                ldsm_x4_t(smem_u32(&Bs[0][ks + fb_krow][fb_n + np * 16]),
                          bh[np*2][0], bh[np*2][1], bh[np*2+1][0], bh[np*2+1][1]);
                ldsm_x4_t(smem_u32(&Bs[1][ks + fb_krow][fb_n + np * 16]),
                          bl[np*2][0], bl[np*2][1], bl[np*2+1][0], bl[np*2+1][1]);
            }
#pragma unroll
            for (int mt = 0; mt < 2; mt++)
#pragma unroll
                for (int nt = 0; nt < 8; nt++) {
                    mma_bf16(acc[mt][nt], ah[mt], bh[nt]);
                    mma_bf16(acc[mt][nt], ah[mt], bl[nt]);
                    mma_bf16(acc[mt][nt], al[mt], bh[nt]);
                }
        }
        __syncthreads();
    }

    // epilogue
#pragma unroll
    for (int mt = 0; mt < 2; mt++) {
        int r_base = row0 + warp_m * 32 + mt * 16 + (lane >> 2);
#pragma unroll
        for (int nt = 0; nt < 8; nt++) {
            int c = col0 + warp_n * 64 + nt * 8 + (lane & 3) * 2;
            float b0 = bias[c], b1 = bias[c + 1];
            if (r_base < M) {
                float2 v = make_float2(acc[mt][nt][0] + b0, acc[mt][nt][1] + b1);
                *(float2*)&C[(size_t)r_base * Ncols + c] = v;
            }
            if (r_base + 8 < M) {
                float2 v = make_float2(acc[mt][nt][2] + b0, acc[mt][nt][3] + b1);
                *(float2*)&C[(size_t)(r_base + 8) * Ncols + c] = v;
            }
        }
    }
}

// ---------------- attention: one warp per destination node, all 8 heads ----------------
__global__ __launch_bounds__(256) void attn_kernel() {
    int gw = (blockIdx.x * blockDim.x + threadIdx.x) >> 5;
    if (gw >= N_NODES) return;
    const int lane = threadIdx.x & 31;           // lane = head*4 + quarter
    const float scale = 0.17677669529663687f;    // 32^-0.5

    const float* Qp = g_qkv + (size_t)gw * 768 + (lane << 3);
    float q[8];
    {
        float4 q0 = *(const float4*)Qp;
        float4 q1 = *(const float4*)(Qp + 4);
        q[0] = q0.x * scale; q[1] = q0.y * scale; q[2] = q0.z * scale; q[3] = q0.w * scale;
        q[4] = q1.x * scale; q[5] = q1.y * scale; q[6] = q1.z * scale; q[7] = q1.w * scale;
    }

    float m = -INFINITY, l = 0.f;
    float acc[8];
#pragma unroll
    for (int i = 0; i < 8; i++) acc[i] = 0.f;

    const int s0   = g_off[gw];
    const int nloc = g_off[gw + 1] - s0;
    const int ntot = nloc + 1 + NGLOB;

    for (int it = 0; it < ntot; it++) {
        int src;
        if (it < nloc)          src = g_srcbuf[s0 + it];
        else if (it == nloc)    src = gw;
        else                    src = N_NODES + (it - nloc - 1);

        const float* Kp = g_qkv + (size_t)src * 768 + 256 + (lane << 3);
        float4 k0 = *(const float4*)Kp;
        float4 k1 = *(const float4*)(Kp + 4);
        float dot = q[0]*k0.x + q[1]*k0.y + q[2]*k0.z + q[3]*k0.w
                  + q[4]*k1.x + q[5]*k1.y + q[6]*k1.z + q[7]*k1.w;
        dot += __shfl_xor_sync(0xFFFFFFFFu, dot, 1);
        dot += __shfl_xor_sync(0xFFFFFFFFu, dot, 2);

        float mnew = fmaxf(m, dot);
        float corr = __expf(m - mnew);
        float w    = __expf(dot - mnew);
        l = l * corr + w;

        const float* Vp = Kp + 256;
        float4 v0 = *(const float4*)Vp;
        float4 v1 = *(const float4*)(Vp + 4);
        acc[0] = acc[0] * corr + w * v0.x;
        acc[1] = acc[1] * corr + w * v0.y;
        acc[2] = acc[2] * corr + w * v0.z;
        acc[3] = acc[3] * corr + w * v0.w;
        acc[4] = acc[4] * corr + w * v1.x;
        acc[5] = acc[5] * corr + w * v1.y;
        acc[6] = acc[6] * corr + w * v1.z;
        acc[7] = acc[7] * corr + w * v1.w;
        m = mnew;
    }

    float inv = 1.f / l;
    float* outp = g_attn + (size_t)gw * 256 + (lane << 3);
#pragma unroll
    for (int i = 0; i < 8; i++) outp[i] = acc[i] * inv;
}

// ---------------- launch ----------------
extern "C" void kernel_launch(void* const* d_in, const int* in_sizes, int n_in,
                              void* d_out, int out_size) {
    const float* x      = (const float*)d_in[0];
    const int*   ei     = (const int*)d_in[1];
    const int*   xi     = (const int*)d_in[2];
    const float* W_qkv  = (const float*)d_in[3];
    const float* b_qkv  = (const float*)d_in[4];
    const float* W_out  = (const float*)d_in[5];
    const float* b_out  = (const float*)d_in[6];
    const float* gtok   = (const float*)d_in[7];
    float* out = (float*)d_out;

    float* qkv_ptr;   cudaGetSymbolAddress((void**)&qkv_ptr, g_qkv);
    float* attn_ptr;  cudaGetSymbolAddress((void**)&attn_ptr, g_attn);

    // CSR build
    zero_counts_kernel<<<N_NODES / 256, 256>>>();
    count_kernel<<<(E_LOCAL + 255) / 256, 256>>>(ei, xi);
    scan_kernel<<<1, 512>>>();
    fill_kernel<<<(E_LOCAL + 255) / 256, 256>>>(ei, xi);

    // QKV projection: [16388, 256] x [256, 768] + b
    {
        dim3 grid(3 * DIM / 128, (NTOTAL + 127) / 128);
        gemm_bias_tc_kernel<<<grid, 256>>>(x, gtok, N_NODES, NTOTAL, 3 * DIM,
                                           W_qkv, b_qkv, qkv_ptr);
    }

    // attention: one warp per node
    attn_kernel<<<(N_NODES * 32) / 256, 256>>>();

    // out projection: [16384, 256] x [256, 256] + b
    {
        dim3 grid(DIM / 128, N_NODES / 128);
        gemm_bias_tc_kernel<<<grid, 256>>>(attn_ptr, attn_ptr, N_NODES, N_NODES, DIM,
                                           W_out, b_out, out);
    }
}